// round 4
// baseline (speedup 1.0000x reference)
#include <cuda_runtime.h>
#include <cuda_fp16.h>
#include <math.h>

#define NB 512
#define HOR 12

// output layout (floats): I_sim, E_sim, beta.mean, sigma.mean, gamma.mean, Pi.mean
#define OUT_I  0
#define OUT_E  (NB*HOR*256)
#define OUT_BM (2*NB*HOR*256)
#define OUT_PI (OUT_BM + 768)
#define OUT_ZN (768 + 65536)

__device__ float g_hsum[NB*128];
__device__ float g_hm[NB*128];
__device__ float g_beta[NB*256];
__device__ float g_sigma[NB*256];
__device__ float g_gamma[NB*256];
__device__ float g_e0[NB*256];
__device__ __align__(16) __half g_D[(size_t)NB*256*256];

// ---------- generic 64x64 tile GEMM (acc 4x4/thread, 256 threads) ----------
__device__ __forceinline__ void tile_gemm(const float* __restrict__ A, int lda,
                                          const float* __restrict__ W, int ldw,
                                          int B0, int C0, int kb, int kn,
                                          float acc[4][4], float* sa, float* sw) {
    int t = threadIdx.x, rg = t >> 4, cg = t & 15;
    for (int kt = 0; kt < kn; kt += 16) {
        int k0 = kb + kt;
        #pragma unroll
        for (int i = t; i < 64*16; i += 256) {
            int r = i >> 4, kk = i & 15;
            sa[kk*68 + r] = A[(size_t)(B0 + r)*lda + k0 + kk];
        }
        #pragma unroll
        for (int i = t; i < 16*64; i += 256) {
            int kk = i >> 6, c = i & 63;
            sw[kk*64 + c] = W[(size_t)(k0 + kk)*ldw + C0 + c];
        }
        __syncthreads();
        #pragma unroll
        for (int kk = 0; kk < 16; ++kk) {
            float4 a = *(const float4*)&sa[kk*68 + rg*4];
            float4 w = *(const float4*)&sw[kk*64 + cg*4];
            float av[4] = {a.x,a.y,a.z,a.w}, wv[4] = {w.x,w.y,w.z,w.w};
            #pragma unroll
            for (int i = 0; i < 4; i++)
                #pragma unroll
                for (int q = 0; q < 4; q++)
                    acc[i][q] = fmaf(av[i], wv[q], acc[i][q]);
        }
        __syncthreads();
    }
}

// ---------- K0: zero accumulators ----------
__global__ void k0_zero(float* out) {
    int i = blockIdx.x * blockDim.x + threadIdx.x;
    if (i < NB*128) g_hsum[i] = 0.f;
    if (i < OUT_ZN) out[OUT_BM + i] = 0.f;
}

// ---------- K1: hsum += x @ W1 (split-k) ----------
__global__ __launch_bounds__(256) void k1(const float* __restrict__ x,
                                          const float* __restrict__ W1) {
    __shared__ __align__(16) float sa[16*68], sw[16*64];
    float acc[4][4] = {};
    int B0 = blockIdx.y*64, C0 = blockIdx.x*64, kb = blockIdx.z*512;
    tile_gemm(x, 4096, W1, 128, B0, C0, kb, 512, acc, sa, sw);
    int rg = threadIdx.x >> 4, cg = threadIdx.x & 15;
    #pragma unroll
    for (int i = 0; i < 4; i++)
        #pragma unroll
        for (int q = 0; q < 4; q++)
            atomicAdd(&g_hsum[(B0 + rg*4 + i)*128 + C0 + cg*4 + q], acc[i][q]);
}

// ---------- K1b: h = relu(hsum + b1) in place ----------
__global__ void k1b(const float* __restrict__ b1) {
    int i = blockIdx.x * blockDim.x + threadIdx.x;
    if (i < NB*128) g_hsum[i] = fmaxf(g_hsum[i] + b1[i & 127], 0.f);
}

// ---------- K2: params = h @ W2 + b2 -> activations + means ----------
__global__ __launch_bounds__(256) void k2(const float* __restrict__ W2,
                                          const float* __restrict__ b2,
                                          float* out) {
    __shared__ __align__(16) float sa[16*68], sw[16*64];
    float acc[4][4] = {};
    int B0 = blockIdx.y*64, C0 = blockIdx.x*64;
    tile_gemm(g_hsum, 128, W2, 1024, B0, C0, 0, 128, acc, sa, sw);
    int rg = threadIdx.x >> 4, cg = threadIdx.x & 15;
    int grp = C0 >> 8;
    float scl = (grp == 0) ? 3.f : (grp == 3) ? 5.f : 1.f;
    float* dst = (grp == 0) ? g_beta : (grp == 1) ? g_sigma : (grp == 2) ? g_gamma : g_e0;
    #pragma unroll
    for (int i = 0; i < 4; i++) {
        int rb = B0 + rg*4 + i;
        #pragma unroll
        for (int q = 0; q < 4; q++) {
            int cgg = C0 + cg*4 + q;
            float s = scl / (1.f + __expf(-(acc[i][q] + b2[cgg])));
            int col = cgg & 255;
            dst[rb*256 + col] = s;
            if (grp < 3) atomicAdd(&out[OUT_BM + grp*256 + col], s * (1.f/512.f));
        }
    }
}

// ---------- K3: hm = relu(cnn @ M1 + mb1) ----------
__global__ __launch_bounds__(256) void k3(const float* __restrict__ cnn,
                                          const float* __restrict__ M1,
                                          const float* __restrict__ mb1) {
    __shared__ __align__(16) float sa[16*68], sw[16*64];
    float acc[4][4] = {};
    int B0 = blockIdx.y*64, C0 = blockIdx.x*64;
    tile_gemm(cnn, 64, M1, 128, B0, C0, 0, 64, acc, sa, sw);
    int rg = threadIdx.x >> 4, cg = threadIdx.x & 15;
    #pragma unroll
    for (int i = 0; i < 4; i++)
        #pragma unroll
        for (int q = 0; q < 4; q++) {
            int c = C0 + cg*4 + q;
            g_hm[(B0 + rg*4 + i)*128 + c] = fmaxf(acc[i][q] + mb1[c], 0.f);
        }
}

// ---------- K4: logits GEMM + softmax + D(fp16 residual) + Pi.mean ----------
// block = 64 b-rows x one softmax row i (256 j); grid (256 i, 8 btile)
#define K4_SMEM ((64*68 + 64*256 + 8*256)*4)
__global__ __launch_bounds__(256) void k4(const float* __restrict__ M2,
                                          const float* __restrict__ mb2,
                                          float* out) {
    extern __shared__ __align__(16) float sm4[];
    float* hmt  = sm4;                    // [kk 64][b 68]
    float* m2s  = sm4 + 64*68;            // [kk 64][j 256]
    float* psum = sm4 + 64*68 + 64*256;   // [rg 8][j 256]
    int t = threadIdx.x, rg = t >> 5, cg = t & 31;
    int r0 = rg * 8, icol = blockIdx.x, B0 = blockIdx.y * 64;

    float accA[8][4] = {}, accB[8][4] = {};
    for (int kh = 0; kh < 2; ++kh) {
        int k0 = kh * 64;
        for (int idx = t; idx < 64*64; idx += 256) {
            int b = idx >> 6, kk = idx & 63;
            hmt[kk*68 + b] = g_hm[(B0 + b)*128 + k0 + kk];
        }
        for (int idx = t; idx < 64*256; idx += 256) {
            int kk = idx >> 8, j = idx & 255;
            m2s[kk*256 + j] = M2[(size_t)(k0 + kk)*65536 + (size_t)icol*256 + j];
        }
        __syncthreads();
        #pragma unroll 4
        for (int kk = 0; kk < 64; ++kk) {
            float4 a0 = *(const float4*)&hmt[kk*68 + r0];
            float4 a1 = *(const float4*)&hmt[kk*68 + r0 + 4];
            float4 bA = *(const float4*)&m2s[kk*256 + 4*cg];
            float4 bB = *(const float4*)&m2s[kk*256 + 128 + 4*cg];
            float av[8] = {a0.x,a0.y,a0.z,a0.w,a1.x,a1.y,a1.z,a1.w};
            float va[4] = {bA.x,bA.y,bA.z,bA.w}, vb[4] = {bB.x,bB.y,bB.z,bB.w};
            #pragma unroll
            for (int i = 0; i < 8; i++)
                #pragma unroll
                for (int q = 0; q < 4; q++) {
                    accA[i][q] = fmaf(av[i], va[q], accA[i][q]);
                    accB[i][q] = fmaf(av[i], vb[q], accB[i][q]);
                }
        }
        __syncthreads();
    }
    float4 mA = *(const float4*)&mb2[(size_t)icol*256 + 4*cg];
    float4 mB = *(const float4*)&mb2[(size_t)icol*256 + 128 + 4*cg];
    float mba[4] = {mA.x,mA.y,mA.z,mA.w}, mbb[4] = {mB.x,mB.y,mB.z,mB.w};
    float pmA[4] = {}, pmB[4] = {};
    #pragma unroll
    for (int i = 0; i < 8; i++) {
        float eA[4], eB[4], s = 0.f;
        #pragma unroll
        for (int q = 0; q < 4; q++) {
            eA[q] = __expf(accA[i][q] + mba[q]);
            eB[q] = __expf(accB[i][q] + mbb[q]);
            s += eA[q] + eB[q];
        }
        #pragma unroll
        for (int o = 16; o > 0; o >>= 1) s += __shfl_xor_sync(0xffffffffu, s, o);
        float inv = 1.f / s, inv256 = inv * 256.f;
        int b = B0 + r0 + i;
        __half* dp = g_D + ((size_t)b*256 + icol)*256;
        float dA[4], dB[4];
        #pragma unroll
        for (int q = 0; q < 4; q++) {
            pmA[q] += eA[q] * inv;  pmB[q] += eB[q] * inv;
            dA[q] = fmaf(eA[q], inv256, -1.f);
            dB[q] = fmaf(eB[q], inv256, -1.f);
        }
        *(__half2*)(dp + 4*cg)           = __floats2half2_rn(dA[0], dA[1]);
        *(__half2*)(dp + 4*cg + 2)       = __floats2half2_rn(dA[2], dA[3]);
        *(__half2*)(dp + 128 + 4*cg)     = __floats2half2_rn(dB[0], dB[1]);
        *(__half2*)(dp + 128 + 4*cg + 2) = __floats2half2_rn(dB[2], dB[3]);
    }
    *(float4*)&psum[rg*256 + 4*cg]       = make_float4(pmA[0], pmA[1], pmA[2], pmA[3]);
    *(float4*)&psum[rg*256 + 128 + 4*cg] = make_float4(pmB[0], pmB[1], pmB[2], pmB[3]);
    __syncthreads();
    float s2 = 0.f;
    #pragma unroll
    for (int g = 0; g < 8; g++) s2 += psum[g*256 + t];
    atomicAdd(&out[OUT_PI + icol*256 + t], s2 * (1.f/512.f));
}

// ---------- K5: RK4 SEIR sim, 1 CTA = 1 batch elem, D in SMEM ----------
#define K5_SMEM (131072 + 1024 + 2048 + 32)
__global__ __launch_bounds__(256) void k5(const float* __restrict__ x,
                                          float* __restrict__ out) {
    extern __shared__ __align__(16) char sm5[];
    __half2* Dsh   = (__half2*)sm5;               // [n 256][cp 128]
    __half2* Ih2   = (__half2*)(sm5 + 131072);    // 256
    float2*  fpart = (float2*) (sm5 + 132096);    // [h 2][cp 128]
    float*   red   = (float*)  (sm5 + 134144);    // 8
    int t = threadIdx.x, b = blockIdx.x;
    {
        const uint4* src = (const uint4*)(g_D + (size_t)b*65536);
        uint4* dst = (uint4*)sm5;
        for (int i = t; i < 8192; i += 256) dst[i] = src[i];
    }
    float beta = g_beta[b*256 + t], sg = g_sigma[b*256 + t];
    float gm   = g_gamma[b*256 + t], e0r = g_e0[b*256 + t];
    float I = fmaxf(x[(size_t)b*4096 + 15*256 + t], 1e-6f);
    float E = I * e0r;
    float S = fmaxf(1.f - E - I, 0.01f);
    __syncthreads();

    const int h = t >> 7, cp = t & 127;
    const __half2* Drow  = Dsh + h*128*128 + cp;
    const __half2* Ibase = Ih2 + h*128;

    auto force = [&](float Iv) -> float {
        Ih2[t] = __float2half2_rn(Iv);
        float s = Iv;
        #pragma unroll
        for (int o = 16; o > 0; o >>= 1) s += __shfl_xor_sync(0xffffffffu, s, o);
        if ((t & 31) == 0) red[t >> 5] = s;
        __syncthreads();
        float sumI = red[0]+red[1]+red[2]+red[3]+red[4]+red[5]+red[6]+red[7];
        __half2 acc = __float2half2_rn(0.f);
        #pragma unroll 4
        for (int n = 0; n < 128; n += 4) {
            uint4 iv = *(const uint4*)(Ibase + n);
            acc = __hfma2(*(__half2*)&iv.x, Drow[(n+0)*128], acc);
            acc = __hfma2(*(__half2*)&iv.y, Drow[(n+1)*128], acc);
            acc = __hfma2(*(__half2*)&iv.z, Drow[(n+2)*128], acc);
            acc = __hfma2(*(__half2*)&iv.w, Drow[(n+3)*128], acc);
        }
        fpart[h*128 + cp] = __half22float2(acc);
        __syncthreads();
        float2 q0 = fpart[t >> 1], q1 = fpart[128 + (t >> 1)];
        float r = (t & 1) ? (q0.y + q1.y) : (q0.x + q1.x);
        __syncthreads();
        return (sumI + r) * (1.f/256.f);
    };

    for (int w = 0; w < HOR; ++w) {
        for (int st = 0; st < 4; ++st) {
            float f1 = force(I);
            float ni = beta * S * f1;
            float dS1 = -ni, dE1 = ni - sg*E, dI1 = sg*E - gm*I;
            float S2 = S + 0.125f*dS1, E2 = E + 0.125f*dE1, I2 = I + 0.125f*dI1;
            float f2 = force(I2); ni = beta * S2 * f2;
            float dS2 = -ni, dE2 = ni - sg*E2, dI2 = sg*E2 - gm*I2;
            float S3 = S + 0.125f*dS2, E3 = E + 0.125f*dE2, I3 = I + 0.125f*dI2;
            float f3 = force(I3); ni = beta * S3 * f3;
            float dS3 = -ni, dE3 = ni - sg*E3, dI3 = sg*E3 - gm*I3;
            float S4 = S + 0.25f*dS3, E4 = E + 0.25f*dE3, I4 = I + 0.25f*dI3;
            float f4 = force(I4); ni = beta * S4 * f4;
            float dS4 = -ni, dE4 = ni - sg*E4, dI4 = sg*E4 - gm*I4;
            const float c = 0.25f / 6.f;
            S = fminf(fmaxf(S + c*(dS1 + 2.f*dS2 + 2.f*dS3 + dS4), 0.f), 1.f);
            E = fminf(fmaxf(E + c*(dE1 + 2.f*dE2 + 2.f*dE3 + dE4), 0.f), 1.f);
            I = fminf(fmaxf(I + c*(dI1 + 2.f*dI2 + 2.f*dI3 + dI4), 0.f), 1.f);
        }
        out[OUT_I + ((size_t)b*HOR + w)*256 + t] = I;
        out[OUT_E + ((size_t)b*HOR + w)*256 + t] = E;
    }
}

extern "C" void kernel_launch(void* const* d_in, const int* in_sizes, int n_in,
                              void* d_out, int out_size) {
    const float* x    = (const float*)d_in[0];
    const float* cnn  = (const float*)d_in[1];
    const float* W1   = (const float*)d_in[2];
    const float* b1   = (const float*)d_in[3];
    const float* W2   = (const float*)d_in[4];
    const float* b2   = (const float*)d_in[5];
    const float* M1   = (const float*)d_in[6];
    const float* mb1  = (const float*)d_in[7];
    const float* M2   = (const float*)d_in[8];
    const float* mb2  = (const float*)d_in[9];
    float* out = (float*)d_out;

    static bool attr_done = false;
    if (!attr_done) {
        cudaFuncSetAttribute(k4, cudaFuncAttributeMaxDynamicSharedMemorySize, K4_SMEM);
        cudaFuncSetAttribute(k5, cudaFuncAttributeMaxDynamicSharedMemorySize, K5_SMEM);
        attr_done = true;
    }

    k0_zero<<<(OUT_ZN + 255)/256, 256>>>(out);
    k1<<<dim3(2, 8, 8), 256>>>(x, W1);
    k1b<<<(NB*128 + 255)/256, 256>>>(b1);
    k2<<<dim3(16, 8), 256>>>(W2, b2, out);
    k3<<<dim3(2, 8), 256>>>(cnn, M1, mb1);
    k4<<<dim3(256, 8), 256, K4_SMEM>>>(M2, mb2, out);
    k5<<<512, 256, K5_SMEM>>>(x, out);
}

// round 5
// speedup vs baseline: 2.7851x; 2.7851x over previous
#include <cuda_runtime.h>
#include <cuda_fp16.h>
#include <math.h>

#define NB 512
#define HOR 12

// output layout (floats): I_sim, E_sim, beta.mean, sigma.mean, gamma.mean, Pi.mean
#define OUT_I  0
#define OUT_E  (NB*HOR*256)
#define OUT_BM (2*NB*HOR*256)
#define OUT_PI (OUT_BM + 768)
#define OUT_ZN (768 + 65536)

__device__ float g_hsum[NB*128];
__device__ float g_hm[NB*128];
__device__ float g_beta[NB*256];
__device__ float g_sigma[NB*256];
__device__ float g_gamma[NB*256];
__device__ float g_e0[NB*256];
__device__ __align__(16) __half g_D[(size_t)NB*256*256];   // D = 256*Pi - 1, [b][n][m]

// ---------- generic 64x64 tile GEMM (acc 4x4/thread, 256 threads) ----------
__device__ __forceinline__ void tile_gemm(const float* __restrict__ A, int lda,
                                          const float* __restrict__ W, int ldw,
                                          int B0, int C0, int kb, int kn,
                                          float acc[4][4], float* sa, float* sw) {
    int t = threadIdx.x, rg = t >> 4, cg = t & 15;
    for (int kt = 0; kt < kn; kt += 16) {
        int k0 = kb + kt;
        #pragma unroll
        for (int i = t; i < 64*16; i += 256) {
            int r = i >> 4, kk = i & 15;
            sa[kk*68 + r] = A[(size_t)(B0 + r)*lda + k0 + kk];
        }
        #pragma unroll
        for (int i = t; i < 16*64; i += 256) {
            int kk = i >> 6, c = i & 63;
            sw[kk*64 + c] = W[(size_t)(k0 + kk)*ldw + C0 + c];
        }
        __syncthreads();
        #pragma unroll
        for (int kk = 0; kk < 16; ++kk) {
            float4 a = *(const float4*)&sa[kk*68 + rg*4];
            float4 w = *(const float4*)&sw[kk*64 + cg*4];
            float av[4] = {a.x,a.y,a.z,a.w}, wv[4] = {w.x,w.y,w.z,w.w};
            #pragma unroll
            for (int i = 0; i < 4; i++)
                #pragma unroll
                for (int q = 0; q < 4; q++)
                    acc[i][q] = fmaf(av[i], wv[q], acc[i][q]);
        }
        __syncthreads();
    }
}

// ---------- K0: zero accumulators ----------
__global__ void k0_zero(float* out) {
    int i = blockIdx.x * blockDim.x + threadIdx.x;
    if (i < NB*128) g_hsum[i] = 0.f;
    if (i < OUT_ZN) out[OUT_BM + i] = 0.f;
}

// ---------- K1: hsum += x @ W1 (split-k) ----------
__global__ __launch_bounds__(256) void k1(const float* __restrict__ x,
                                          const float* __restrict__ W1) {
    __shared__ __align__(16) float sa[16*68], sw[16*64];
    float acc[4][4] = {};
    int B0 = blockIdx.y*64, C0 = blockIdx.x*64, kb = blockIdx.z*512;
    tile_gemm(x, 4096, W1, 128, B0, C0, kb, 512, acc, sa, sw);
    int rg = threadIdx.x >> 4, cg = threadIdx.x & 15;
    #pragma unroll
    for (int i = 0; i < 4; i++)
        #pragma unroll
        for (int q = 0; q < 4; q++)
            atomicAdd(&g_hsum[(B0 + rg*4 + i)*128 + C0 + cg*4 + q], acc[i][q]);
}

// ---------- K1b: h = relu(hsum + b1) in place ----------
__global__ void k1b(const float* __restrict__ b1) {
    int i = blockIdx.x * blockDim.x + threadIdx.x;
    if (i < NB*128) g_hsum[i] = fmaxf(g_hsum[i] + b1[i & 127], 0.f);
}

// ---------- K2: params = h @ W2 + b2 -> activations + means ----------
__global__ __launch_bounds__(256) void k2(const float* __restrict__ W2,
                                          const float* __restrict__ b2,
                                          float* out) {
    __shared__ __align__(16) float sa[16*68], sw[16*64];
    float acc[4][4] = {};
    int B0 = blockIdx.y*64, C0 = blockIdx.x*64;
    tile_gemm(g_hsum, 128, W2, 1024, B0, C0, 0, 128, acc, sa, sw);
    int rg = threadIdx.x >> 4, cg = threadIdx.x & 15;
    int grp = C0 >> 8;
    float scl = (grp == 0) ? 3.f : (grp == 3) ? 5.f : 1.f;
    float* dst = (grp == 0) ? g_beta : (grp == 1) ? g_sigma : (grp == 2) ? g_gamma : g_e0;
    #pragma unroll
    for (int i = 0; i < 4; i++) {
        int rb = B0 + rg*4 + i;
        #pragma unroll
        for (int q = 0; q < 4; q++) {
            int cgg = C0 + cg*4 + q;
            float s = scl / (1.f + __expf(-(acc[i][q] + b2[cgg])));
            int col = cgg & 255;
            dst[rb*256 + col] = s;
            if (grp < 3) atomicAdd(&out[OUT_BM + grp*256 + col], s * (1.f/512.f));
        }
    }
}

// ---------- K3: hm = relu(cnn @ M1 + mb1) ----------
__global__ __launch_bounds__(256) void k3(const float* __restrict__ cnn,
                                          const float* __restrict__ M1,
                                          const float* __restrict__ mb1) {
    __shared__ __align__(16) float sa[16*68], sw[16*64];
    float acc[4][4] = {};
    int B0 = blockIdx.y*64, C0 = blockIdx.x*64;
    tile_gemm(cnn, 64, M1, 128, B0, C0, 0, 64, acc, sa, sw);
    int rg = threadIdx.x >> 4, cg = threadIdx.x & 15;
    #pragma unroll
    for (int i = 0; i < 4; i++)
        #pragma unroll
        for (int q = 0; q < 4; q++) {
            int c = C0 + cg*4 + q;
            g_hm[(B0 + rg*4 + i)*128 + c] = fmaxf(acc[i][q] + mb1[c], 0.f);
        }
}

// ---------- K4: logits GEMM (fp16 HFMA2) + softmax + D(fp16) + Pi.mean ----------
// block = 64 b-rows x one softmax row i (256 j); grid (256 i, 8 btile)
// smem: hmt2 half2[64][68] (dup), m2h half2[64][128] (j-pairs), psum float[8][256]
#define K4_SMEM ((64*68 + 64*128 + 8*256) * 4)
__global__ __launch_bounds__(256) void k4(const float* __restrict__ M2,
                                          const float* __restrict__ mb2,
                                          float* out) {
    extern __shared__ __align__(16) char sm4raw[];
    __half2* hmt2 = (__half2*)sm4raw;                         // [kk][b]
    __half2* m2h  = (__half2*)(sm4raw + 64*68*4);             // [kk][pair]
    float*   psum = (float*)(sm4raw + (64*68 + 64*128)*4);    // [rg][j]
    int t = threadIdx.x, rg = t >> 5, cg = t & 31;
    int r0 = rg * 8, icol = blockIdx.x, B0 = blockIdx.y * 64;

    __half2 accA[8][2], accB[8][2];
    #pragma unroll
    for (int i = 0; i < 8; i++) {
        accA[i][0] = accA[i][1] = __float2half2_rn(0.f);
        accB[i][0] = accB[i][1] = __float2half2_rn(0.f);
    }

    for (int kh = 0; kh < 2; ++kh) {
        int k0 = kh * 64;
        for (int idx = t; idx < 64*64; idx += 256) {
            int kk = idx & 63, bb = idx >> 6;
            hmt2[kk*68 + bb] = __float2half2_rn(g_hm[(B0 + bb)*128 + k0 + kk]);
        }
        for (int idx = t; idx < 64*128; idx += 256) {
            int kk = idx >> 7, p = idx & 127;
            float2 v = *(const float2*)&M2[(size_t)(k0 + kk)*65536 + (size_t)icol*256 + 2*p];
            m2h[kk*128 + p] = __float22half2_rn(v);
        }
        __syncthreads();
        #pragma unroll 4
        for (int kk = 0; kk < 64; ++kk) {
            uint4 A0 = *(const uint4*)&hmt2[kk*68 + r0];
            uint4 A1 = *(const uint4*)&hmt2[kk*68 + r0 + 4];
            __half2 a[8];
            a[0] = *(__half2*)&A0.x; a[1] = *(__half2*)&A0.y;
            a[2] = *(__half2*)&A0.z; a[3] = *(__half2*)&A0.w;
            a[4] = *(__half2*)&A1.x; a[5] = *(__half2*)&A1.y;
            a[6] = *(__half2*)&A1.z; a[7] = *(__half2*)&A1.w;
            __half2 bA0 = m2h[kk*128 + 2*cg], bA1 = m2h[kk*128 + 2*cg + 1];
            __half2 bB0 = m2h[kk*128 + 64 + 2*cg], bB1 = m2h[kk*128 + 64 + 2*cg + 1];
            #pragma unroll
            for (int i = 0; i < 8; i++) {
                accA[i][0] = __hfma2(a[i], bA0, accA[i][0]);
                accA[i][1] = __hfma2(a[i], bA1, accA[i][1]);
                accB[i][0] = __hfma2(a[i], bB0, accB[i][0]);
                accB[i][1] = __hfma2(a[i], bB1, accB[i][1]);
            }
        }
        __syncthreads();
    }

    float4 mA = *(const float4*)&mb2[(size_t)icol*256 + 4*cg];
    float4 mB = *(const float4*)&mb2[(size_t)icol*256 + 128 + 4*cg];
    float mba[4] = {mA.x,mA.y,mA.z,mA.w}, mbb[4] = {mB.x,mB.y,mB.z,mB.w};
    float pmA[4] = {}, pmB[4] = {};
    #pragma unroll
    for (int i = 0; i < 8; i++) {
        float2 fA0 = __half22float2(accA[i][0]);
        float2 fA1 = __half22float2(accA[i][1]);
        float2 fB0 = __half22float2(accB[i][0]);
        float2 fB1 = __half22float2(accB[i][1]);
        float lA[4] = {fA0.x, fA0.y, fA1.x, fA1.y};
        float lB[4] = {fB0.x, fB0.y, fB1.x, fB1.y};
        float eA[4], eB[4], s = 0.f;
        #pragma unroll
        for (int q = 0; q < 4; q++) {
            eA[q] = __expf(lA[q] + mba[q]);
            eB[q] = __expf(lB[q] + mbb[q]);
            s += eA[q] + eB[q];
        }
        #pragma unroll
        for (int o = 16; o > 0; o >>= 1) s += __shfl_xor_sync(0xffffffffu, s, o);
        float inv = 1.f / s, inv256 = inv * 256.f;
        int b = B0 + r0 + i;
        __half* dp = g_D + ((size_t)b*256 + icol)*256;
        float dA[4], dB[4];
        #pragma unroll
        for (int q = 0; q < 4; q++) {
            pmA[q] += eA[q] * inv;  pmB[q] += eB[q] * inv;
            dA[q] = fmaf(eA[q], inv256, -1.f);
            dB[q] = fmaf(eB[q], inv256, -1.f);
        }
        *(__half2*)(dp + 4*cg)           = __floats2half2_rn(dA[0], dA[1]);
        *(__half2*)(dp + 4*cg + 2)       = __floats2half2_rn(dA[2], dA[3]);
        *(__half2*)(dp + 128 + 4*cg)     = __floats2half2_rn(dB[0], dB[1]);
        *(__half2*)(dp + 128 + 4*cg + 2) = __floats2half2_rn(dB[2], dB[3]);
    }
    *(float4*)&psum[rg*256 + 4*cg]       = make_float4(pmA[0], pmA[1], pmA[2], pmA[3]);
    *(float4*)&psum[rg*256 + 128 + 4*cg] = make_float4(pmB[0], pmB[1], pmB[2], pmB[3]);
    __syncthreads();
    float s2 = 0.f;
    #pragma unroll
    for (int g = 0; g < 8; g++) s2 += psum[g*256 + t];
    atomicAdd(&out[OUT_PI + icol*256 + t], s2 * (1.f/512.f));
}

// ---------- K5: RK4 SEIR sim, register-resident int8 D + DP4A ----------
// 1 CTA = 1 batch elem, thread t owns column m=t of D in 64 packed int8 regs.
// force_m = (sumI + Ibar*C_m + dp4a(dI_q, D_q)*sD*sI) / 256,  C_m exact fp32 colsum.
__global__ __launch_bounds__(256, 2) void k5(const float* __restrict__ x,
                                             float* __restrict__ out) {
    __shared__ float red[8];
    __shared__ float rmax[8];
    __shared__ __align__(16) unsigned Ipk[64];
    int t = threadIdx.x, b = blockIdx.x;
    int lane = t & 31, warp = t >> 5;

    const __half* Dg = g_D + (size_t)b * 65536 + t;   // column m=t, stride 256

    // pass 1: fp32 column sum + CTA max|D|
    float C = 0.f, mx = 0.f;
    #pragma unroll 8
    for (int n = 0; n < 256; ++n) {
        float v = __half2float(__ldg(Dg + (size_t)n * 256));
        C += v; mx = fmaxf(mx, fabsf(v));
    }
    #pragma unroll
    for (int o = 16; o > 0; o >>= 1) mx = fmaxf(mx, __shfl_xor_sync(0xffffffffu, mx, o));
    if (lane == 0) rmax[warp] = mx;
    __syncthreads();
    float m8 = rmax[0];
    #pragma unroll
    for (int w = 1; w < 8; ++w) m8 = fmaxf(m8, rmax[w]);
    float sD = fmaxf(m8, 1e-8f) * (1.f/127.f);
    float invsD = 1.f / sD;
    const float fscale = sD * (1.f/127.f);

    // pass 2: quantize column into 64 packed int8 words (registers)
    unsigned qw[64];
    #pragma unroll
    for (int g = 0; g < 64; ++g) {
        unsigned w = 0;
        #pragma unroll
        for (int kk = 0; kk < 4; ++kk) {
            float v = __half2float(__ldg(Dg + (size_t)(g*4 + kk) * 256));
            int q = __float2int_rn(v * invsD);
            q = max(-127, min(127, q));
            w |= ((unsigned)(q & 255)) << (8*kk);
        }
        qw[g] = w;
    }

    float beta = g_beta[b*256 + t], sg = g_sigma[b*256 + t];
    float gm   = g_gamma[b*256 + t], e0r = g_e0[b*256 + t];
    float I = fmaxf(x[(size_t)b*4096 + 15*256 + t], 1e-6f);
    float E = I * e0r;
    float S = fmaxf(1.f - E - I, 0.01f);
    __syncthreads();

    auto force = [&](float Iv) -> float {
        float s = Iv;
        #pragma unroll
        for (int o = 16; o > 0; o >>= 1) s += __shfl_xor_sync(0xffffffffu, s, o);
        if (lane == 0) red[warp] = s;
        __syncthreads();
        float sumI = red[0]+red[1]+red[2]+red[3]+red[4]+red[5]+red[6]+red[7];
        float Ibar = sumI * (1.f/256.f);
        int qi = __float2int_rn((Iv - Ibar) * 127.f);
        qi = max(-127, min(127, qi));
        ((signed char*)Ipk)[t] = (signed char)qi;
        __syncthreads();
        int a0 = 0, a1 = 0, a2 = 0, a3 = 0;
        #pragma unroll
        for (int g = 0; g < 64; g += 4) {
            uint4 w = *(const uint4*)&Ipk[g];
            a0 = __dp4a((int)w.x, (int)qw[g+0], a0);
            a1 = __dp4a((int)w.y, (int)qw[g+1], a1);
            a2 = __dp4a((int)w.z, (int)qw[g+2], a2);
            a3 = __dp4a((int)w.w, (int)qw[g+3], a3);
        }
        float resid = (float)(a0 + a1 + a2 + a3) * fscale;
        return (sumI + Ibar * C + resid) * (1.f/256.f);
    };

    for (int w = 0; w < HOR; ++w) {
        for (int st = 0; st < 4; ++st) {
            float f1 = force(I);
            float ni = beta * S * f1;
            float dS1 = -ni, dE1 = ni - sg*E, dI1 = sg*E - gm*I;
            float S2 = S + 0.125f*dS1, E2 = E + 0.125f*dE1, I2 = I + 0.125f*dI1;
            float f2 = force(I2); ni = beta * S2 * f2;
            float dS2 = -ni, dE2 = ni - sg*E2, dI2 = sg*E2 - gm*I2;
            float S3 = S + 0.125f*dS2, E3 = E + 0.125f*dE2, I3 = I + 0.125f*dI2;
            float f3 = force(I3); ni = beta * S3 * f3;
            float dS3 = -ni, dE3 = ni - sg*E3, dI3 = sg*E3 - gm*I3;
            float S4 = S + 0.25f*dS3, E4 = E + 0.25f*dE3, I4 = I + 0.25f*dI3;
            float f4 = force(I4); ni = beta * S4 * f4;
            float dS4 = -ni, dE4 = ni - sg*E4, dI4 = sg*E4 - gm*I4;
            const float c = 0.25f / 6.f;
            S = fminf(fmaxf(S + c*(dS1 + 2.f*dS2 + 2.f*dS3 + dS4), 0.f), 1.f);
            E = fminf(fmaxf(E + c*(dE1 + 2.f*dE2 + 2.f*dE3 + dE4), 0.f), 1.f);
            I = fminf(fmaxf(I + c*(dI1 + 2.f*dI2 + 2.f*dI3 + dI4), 0.f), 1.f);
        }
        out[OUT_I + ((size_t)b*HOR + w)*256 + t] = I;
        out[OUT_E + ((size_t)b*HOR + w)*256 + t] = E;
    }
}

extern "C" void kernel_launch(void* const* d_in, const int* in_sizes, int n_in,
                              void* d_out, int out_size) {
    const float* x    = (const float*)d_in[0];
    const float* cnn  = (const float*)d_in[1];
    const float* W1   = (const float*)d_in[2];
    const float* b1   = (const float*)d_in[3];
    const float* W2   = (const float*)d_in[4];
    const float* b2   = (const float*)d_in[5];
    const float* M1   = (const float*)d_in[6];
    const float* mb1  = (const float*)d_in[7];
    const float* M2   = (const float*)d_in[8];
    const float* mb2  = (const float*)d_in[9];
    float* out = (float*)d_out;

    static cudaStream_t s2 = nullptr;
    static cudaEvent_t evA = nullptr, evB = nullptr;
    if (!s2) {
        cudaStreamCreateWithFlags(&s2, cudaStreamNonBlocking);
        cudaEventCreateWithFlags(&evA, cudaEventDisableTiming);
        cudaEventCreateWithFlags(&evB, cudaEventDisableTiming);
        cudaFuncSetAttribute(k4, cudaFuncAttributeMaxDynamicSharedMemorySize, K4_SMEM);
    }

    k0_zero<<<(OUT_ZN + 255)/256, 256>>>(out);
    cudaEventRecord(evA, 0);
    cudaStreamWaitEvent(s2, evA, 0);

    // mobility branch on s2
    k3<<<dim3(2, 8), 256, 0, s2>>>(cnn, M1, mb1);
    k4<<<dim3(256, 8), 256, K4_SMEM, s2>>>(M2, mb2, out);
    cudaEventRecord(evB, s2);

    // param branch on main stream
    k1<<<dim3(2, 8, 8), 256>>>(x, W1);
    k1b<<<(NB*128 + 255)/256, 256>>>(b1);
    k2<<<dim3(16, 8), 256>>>(W2, b2, out);

    cudaStreamWaitEvent(0, evB, 0);
    k5<<<512, 256>>>(x, out);
}

// round 6
// speedup vs baseline: 3.5164x; 1.2625x over previous
#include <cuda_runtime.h>
#include <cuda_fp16.h>
#include <math.h>

#define NB 512
#define HOR 12

// output layout (floats): I_sim, E_sim, beta.mean, sigma.mean, gamma.mean, Pi.mean
#define OUT_I  0
#define OUT_E  (NB*HOR*256)
#define OUT_BM (2*NB*HOR*256)
#define OUT_PI (OUT_BM + 768)
#define OUT_ZN (768 + 65536)

__device__ float g_hsum[NB*128];                 // param hidden (post-relu)
__device__ float g_hm[NB*128];                   // mobility hidden
__device__ float g_beta[NB*256];
__device__ float g_sigma[NB*256];
__device__ float g_gamma[NB*256];
__device__ float g_e0[NB*256];
__device__ __align__(16) __half g_D[(size_t)NB*256*256];   // D = 256*Pi - 1
__device__ float g_part[64*65536];               // k1 split-k partials (16 MB)
__device__ unsigned g_qh[NB*32];                 // int8-packed hm rows
__device__ float g_sh[NB];                       // hm row scales
__device__ __align__(16) unsigned g_qm[(size_t)256*8192];  // int8 M2, [icol][q][j]
__device__ float g_sm[65536];                    // M2 column scales

// ---------- K0: zero output means region ----------
__global__ void k0_zero(float* out) {
    int i = blockIdx.x * blockDim.x + threadIdx.x;
    if (i < OUT_ZN) out[OUT_BM + i] = 0.f;
}

// ---------- K1: partials[kz] = x @ W1 chunk (tile 128x128, acc 8x8) ----------
// grid (4 btile, 64 ksplit); CTA: rows B0..+128, all 128 cols, k = kz*64..+64
__global__ __launch_bounds__(256) void k1(const float* __restrict__ x,
                                          const float* __restrict__ W1) {
    __shared__ __align__(16) float sa[16*132];   // [kk][row 128 pad 132]
    __shared__ __align__(16) float sw[16*128];   // [kk][col]
    int t = threadIdx.x, rg = t >> 4, cg = t & 15;
    int B0 = blockIdx.x * 128, kz = blockIdx.y;
    float acc[8][8] = {};
    for (int kt = 0; kt < 4; ++kt) {
        int k0 = kz*64 + kt*16;
        #pragma unroll
        for (int i = t; i < 512; i += 256) {
            int r = i >> 2, kq = i & 3;
            float4 v = *(const float4*)&x[(size_t)(B0 + r)*4096 + k0 + kq*4];
            sa[(kq*4+0)*132 + r] = v.x;
            sa[(kq*4+1)*132 + r] = v.y;
            sa[(kq*4+2)*132 + r] = v.z;
            sa[(kq*4+3)*132 + r] = v.w;
        }
        #pragma unroll
        for (int i = t; i < 512; i += 256) {
            int kk = i >> 5, c4 = i & 31;
            *(float4*)&sw[kk*128 + c4*4] =
                *(const float4*)&W1[(size_t)(k0 + kk)*128 + c4*4];
        }
        __syncthreads();
        #pragma unroll
        for (int kk = 0; kk < 16; ++kk) {
            float4 a0 = *(const float4*)&sa[kk*132 + rg*8];
            float4 a1 = *(const float4*)&sa[kk*132 + rg*8 + 4];
            float4 b0 = *(const float4*)&sw[kk*128 + cg*8];
            float4 b1 = *(const float4*)&sw[kk*128 + cg*8 + 4];
            float av[8] = {a0.x,a0.y,a0.z,a0.w,a1.x,a1.y,a1.z,a1.w};
            float bv[8] = {b0.x,b0.y,b0.z,b0.w,b1.x,b1.y,b1.z,b1.w};
            #pragma unroll
            for (int i = 0; i < 8; i++)
                #pragma unroll
                for (int q = 0; q < 8; q++)
                    acc[i][q] = fmaf(av[i], bv[q], acc[i][q]);
        }
        __syncthreads();
    }
    float* dst = g_part + (size_t)kz*65536;
    #pragma unroll
    for (int i = 0; i < 8; i++) {
        int r = B0 + rg*8 + i;
        *(float4*)&dst[r*128 + cg*8]     = make_float4(acc[i][0],acc[i][1],acc[i][2],acc[i][3]);
        *(float4*)&dst[r*128 + cg*8 + 4] = make_float4(acc[i][4],acc[i][5],acc[i][6],acc[i][7]);
    }
}

// ---------- K1b: h = relu(sum_k partials + b1) ----------
__global__ void k1b(const float* __restrict__ b1) {
    int i = blockIdx.x * blockDim.x + threadIdx.x;
    float s = 0.f;
    #pragma unroll
    for (int ks = 0; ks < 64; ++ks) s += g_part[(size_t)ks*65536 + i];
    g_hsum[i] = fmaxf(s + b1[i & 127], 0.f);
}

// ---------- K2: params = h @ W2 + b2 -> activations + means (tile 64x128) ----------
__global__ __launch_bounds__(256) void k2(const float* __restrict__ W2,
                                          const float* __restrict__ b2,
                                          float* out) {
    __shared__ __align__(16) float sa[16*68];    // [kk][row 64 pad 68]
    __shared__ __align__(16) float sw[16*128];
    int t = threadIdx.x, rg = t >> 4, cg = t & 15;
    int C0 = blockIdx.x * 128, B0 = blockIdx.y * 64;
    float acc[4][8] = {};
    for (int kt = 0; kt < 8; ++kt) {
        int k0 = kt*16;
        {
            int i = t;  // 256 float4 exactly
            int r = i >> 2, kq = i & 3;
            float4 v = *(const float4*)&g_hsum[(B0 + r)*128 + k0 + kq*4];
            sa[(kq*4+0)*68 + r] = v.x;
            sa[(kq*4+1)*68 + r] = v.y;
            sa[(kq*4+2)*68 + r] = v.z;
            sa[(kq*4+3)*68 + r] = v.w;
        }
        #pragma unroll
        for (int i = t; i < 512; i += 256) {
            int kk = i >> 5, c4 = i & 31;
            *(float4*)&sw[kk*128 + c4*4] =
                *(const float4*)&W2[(size_t)(k0 + kk)*1024 + C0 + c4*4];
        }
        __syncthreads();
        #pragma unroll
        for (int kk = 0; kk < 16; ++kk) {
            float4 a  = *(const float4*)&sa[kk*68 + rg*4];
            float4 b0 = *(const float4*)&sw[kk*128 + cg*8];
            float4 b1 = *(const float4*)&sw[kk*128 + cg*8 + 4];
            float av[4] = {a.x,a.y,a.z,a.w};
            float bv[8] = {b0.x,b0.y,b0.z,b0.w,b1.x,b1.y,b1.z,b1.w};
            #pragma unroll
            for (int i = 0; i < 4; i++)
                #pragma unroll
                for (int q = 0; q < 8; q++)
                    acc[i][q] = fmaf(av[i], bv[q], acc[i][q]);
        }
        __syncthreads();
    }
    int grp = C0 >> 8;
    float scl = (grp == 0) ? 3.f : (grp == 3) ? 5.f : 1.f;
    float* dst = (grp == 0) ? g_beta : (grp == 1) ? g_sigma : (grp == 2) ? g_gamma : g_e0;
    #pragma unroll
    for (int i = 0; i < 4; i++) {
        int rb = B0 + rg*4 + i;
        #pragma unroll
        for (int q = 0; q < 8; q++) {
            int cgg = C0 + cg*8 + q;
            float s = scl / (1.f + __expf(-(acc[i][q] + b2[cgg])));
            int col = cgg & 255;
            dst[rb*256 + col] = s;
            if (grp < 3) atomicAdd(&out[OUT_BM + grp*256 + col], s * (1.f/512.f));
        }
    }
}

// ---------- K3: hm = relu(cnn @ M1 + mb1) (64x64 tile, 4x4 acc) ----------
__global__ __launch_bounds__(256) void k3(const float* __restrict__ cnn,
                                          const float* __restrict__ M1,
                                          const float* __restrict__ mb1) {
    __shared__ __align__(16) float sa[16*68], sw[16*64];
    int t = threadIdx.x, rg = t >> 4, cg = t & 15;
    int B0 = blockIdx.y*64, C0 = blockIdx.x*64;
    float acc[4][4] = {};
    for (int kt = 0; kt < 64; kt += 16) {
        #pragma unroll
        for (int i = t; i < 64*16; i += 256) {
            int r = i >> 4, kk = i & 15;
            sa[kk*68 + r] = cnn[(size_t)(B0 + r)*64 + kt + kk];
        }
        #pragma unroll
        for (int i = t; i < 16*64; i += 256) {
            int kk = i >> 6, c = i & 63;
            sw[kk*64 + c] = M1[(size_t)(kt + kk)*128 + C0 + c];
        }
        __syncthreads();
        #pragma unroll
        for (int kk = 0; kk < 16; ++kk) {
            float4 a = *(const float4*)&sa[kk*68 + rg*4];
            float4 w = *(const float4*)&sw[kk*64 + cg*4];
            float av[4] = {a.x,a.y,a.z,a.w}, wv[4] = {w.x,w.y,w.z,w.w};
            #pragma unroll
            for (int i = 0; i < 4; i++)
                #pragma unroll
                for (int q = 0; q < 4; q++)
                    acc[i][q] = fmaf(av[i], wv[q], acc[i][q]);
        }
        __syncthreads();
    }
    #pragma unroll
    for (int i = 0; i < 4; i++)
        #pragma unroll
        for (int q = 0; q < 4; q++) {
            int c = C0 + cg*4 + q;
            g_hm[(B0 + rg*4 + i)*128 + c] = fmaxf(acc[i][q] + mb1[c], 0.f);
        }
}

// ---------- K3b: quantize hm rows to int8 (warp = one row) ----------
__global__ void k3b() {
    int lane = threadIdx.x & 31, warp = threadIdx.x >> 5;
    int row = blockIdx.x*8 + warp;
    float4 v = *(const float4*)&g_hm[row*128 + lane*4];
    float mx = fmaxf(fmaxf(v.x, v.y), fmaxf(v.z, v.w));
    #pragma unroll
    for (int o = 16; o > 0; o >>= 1) mx = fmaxf(mx, __shfl_xor_sync(0xffffffffu, mx, o));
    float inv = mx > 0.f ? 127.f/mx : 0.f;
    int q0 = __float2int_rn(v.x*inv), q1 = __float2int_rn(v.y*inv);
    int q2 = __float2int_rn(v.z*inv), q3 = __float2int_rn(v.w*inv);
    unsigned w = (unsigned)(q0 & 255) | ((unsigned)(q1 & 255) << 8) |
                 ((unsigned)(q2 & 255) << 16) | ((unsigned)(q3 & 255) << 24);
    g_qh[row*32 + lane] = w;
    if (lane == 0) g_sh[row] = mx * (1.f/127.f);
}

// ---------- K3c: quantize M2 per output column -> g_qm[icol][q][j] ----------
__global__ __launch_bounds__(256) void k3c(const float* __restrict__ M2) {
    int j = threadIdx.x, icol = blockIdx.x;
    const float* base = M2 + (size_t)icol*256 + j;
    float mx = 0.f;
    #pragma unroll 8
    for (int k = 0; k < 128; ++k) mx = fmaxf(mx, fabsf(base[(size_t)k*65536]));
    float inv = mx > 0.f ? 127.f/mx : 0.f;
    g_sm[icol*256 + j] = mx * (1.f/127.f);
    for (int q = 0; q < 32; ++q) {
        unsigned w = 0;
        #pragma unroll
        for (int e = 0; e < 4; ++e) {
            float v = base[(size_t)(4*q + e)*65536];
            int qi = __float2int_rn(v*inv);
            qi = max(-127, min(127, qi));
            w |= ((unsigned)(qi & 255)) << (8*e);
        }
        g_qm[(size_t)icol*8192 + q*256 + j] = w;
    }
}

// ---------- K4: int8 DP4A logits + softmax + D(fp16) + Pi.mean ----------
// CTA = (icol, 64 b-rows). thread: 8 b (warp rg) x 8 j (lane cg).
#define K4_SMEM ((64*33 + 32*260 + 8*256 + 64) * 4)
__global__ __launch_bounds__(256) void k4(const float* __restrict__ mb2,
                                          float* out) {
    extern __shared__ __align__(16) char smraw[];
    unsigned* qhS = (unsigned*)smraw;                         // [b][33]
    unsigned* qmS = (unsigned*)(smraw + 64*33*4);             // [q][260]
    float* psum   = (float*)(smraw + (64*33 + 32*260)*4);     // [8][256]
    float* shS    = (float*)(smraw + (64*33 + 32*260 + 2048)*4);
    int t = threadIdx.x, rg = t >> 5, cg = t & 31;
    int icol = blockIdx.x, B0 = blockIdx.y * 64;

    #pragma unroll
    for (int i = t; i < 2048; i += 256) {
        int b = i >> 5, q = i & 31;
        qhS[b*33 + q] = g_qh[(B0 + b)*32 + q];
    }
    {
        const uint4* src = (const uint4*)(g_qm + (size_t)icol*8192);
        #pragma unroll
        for (int i = t; i < 2048; i += 256) {
            int q = i >> 6, j4 = i & 63;
            *(uint4*)&qmS[q*260 + j4*4] = src[i];
        }
    }
    if (t < 64) shS[t] = g_sh[B0 + t];
    __syncthreads();

    int acc[8][8] = {};
    #pragma unroll 4
    for (int q = 0; q < 32; ++q) {
        int a[8];
        #pragma unroll
        for (int i = 0; i < 8; i++) a[i] = (int)qhS[(rg*8 + i)*33 + q];
        uint4 m0 = *(const uint4*)&qmS[q*260 + cg*8];
        uint4 m1 = *(const uint4*)&qmS[q*260 + cg*8 + 4];
        int m[8] = {(int)m0.x,(int)m0.y,(int)m0.z,(int)m0.w,
                    (int)m1.x,(int)m1.y,(int)m1.z,(int)m1.w};
        #pragma unroll
        for (int i = 0; i < 8; i++)
            #pragma unroll
            for (int e = 0; e < 8; e++)
                acc[i][e] = __dp4a(a[i], m[e], acc[i][e]);
    }

    float4 s0 = *(const float4*)&g_sm[icol*256 + cg*8];
    float4 s1 = *(const float4*)&g_sm[icol*256 + cg*8 + 4];
    float4 m0 = *(const float4*)&mb2[(size_t)icol*256 + cg*8];
    float4 m1 = *(const float4*)&mb2[(size_t)icol*256 + cg*8 + 4];
    float smj[8] = {s0.x,s0.y,s0.z,s0.w,s1.x,s1.y,s1.z,s1.w};
    float mbj[8] = {m0.x,m0.y,m0.z,m0.w,m1.x,m1.y,m1.z,m1.w};
    float pm[8] = {};
    #pragma unroll
    for (int i = 0; i < 8; i++) {
        float shr = shS[rg*8 + i];
        float ee[8], s = 0.f;
        #pragma unroll
        for (int e = 0; e < 8; e++) {
            float l = (float)acc[i][e] * (shr * smj[e]) + mbj[e];
            ee[e] = __expf(l);
            s += ee[e];
        }
        #pragma unroll
        for (int o = 16; o > 0; o >>= 1) s += __shfl_xor_sync(0xffffffffu, s, o);
        float inv = 1.f / s, inv256 = inv * 256.f;
        int b = B0 + rg*8 + i;
        __half* dp = g_D + ((size_t)b*256 + icol)*256 + cg*8;
        #pragma unroll
        for (int e = 0; e < 8; e += 2) {
            float d0 = fmaf(ee[e],   inv256, -1.f);
            float d1 = fmaf(ee[e+1], inv256, -1.f);
            *(__half2*)(dp + e) = __floats2half2_rn(d0, d1);
        }
        #pragma unroll
        for (int e = 0; e < 8; e++) pm[e] += ee[e] * inv;
    }
    *(float4*)&psum[rg*256 + cg*8]     = make_float4(pm[0],pm[1],pm[2],pm[3]);
    *(float4*)&psum[rg*256 + cg*8 + 4] = make_float4(pm[4],pm[5],pm[6],pm[7]);
    __syncthreads();
    float s2 = 0.f;
    #pragma unroll
    for (int g = 0; g < 8; g++) s2 += psum[g*256 + t];
    atomicAdd(&out[OUT_PI + icol*256 + t], s2 * (1.f/512.f));
}

// ---------- K5: RK4 SEIR sim, register-resident int8 D + DP4A ----------
__global__ __launch_bounds__(256, 2) void k5(const float* __restrict__ x,
                                             float* __restrict__ out) {
    __shared__ float red[8];
    __shared__ float rmax[8];
    __shared__ __align__(16) unsigned Ipk[64];
    int t = threadIdx.x, b = blockIdx.x;
    int lane = t & 31, warp = t >> 5;

    const __half* Dg = g_D + (size_t)b * 65536 + t;

    float C = 0.f, mx = 0.f;
    #pragma unroll 8
    for (int n = 0; n < 256; ++n) {
        float v = __half2float(__ldg(Dg + (size_t)n * 256));
        C += v; mx = fmaxf(mx, fabsf(v));
    }
    #pragma unroll
    for (int o = 16; o > 0; o >>= 1) mx = fmaxf(mx, __shfl_xor_sync(0xffffffffu, mx, o));
    if (lane == 0) rmax[warp] = mx;
    __syncthreads();
    float m8 = rmax[0];
    #pragma unroll
    for (int w = 1; w < 8; ++w) m8 = fmaxf(m8, rmax[w]);
    float sD = fmaxf(m8, 1e-8f) * (1.f/127.f);
    float invsD = 1.f / sD;
    const float fscale = sD * (1.f/127.f);

    unsigned qw[64];
    #pragma unroll
    for (int g = 0; g < 64; ++g) {
        unsigned w = 0;
        #pragma unroll
        for (int kk = 0; kk < 4; ++kk) {
            float v = __half2float(__ldg(Dg + (size_t)(g*4 + kk) * 256));
            int q = __float2int_rn(v * invsD);
            q = max(-127, min(127, q));
            w |= ((unsigned)(q & 255)) << (8*kk);
        }
        qw[g] = w;
    }

    float beta = g_beta[b*256 + t], sg = g_sigma[b*256 + t];
    float gm   = g_gamma[b*256 + t], e0r = g_e0[b*256 + t];
    float I = fmaxf(x[(size_t)b*4096 + 15*256 + t], 1e-6f);
    float E = I * e0r;
    float S = fmaxf(1.f - E - I, 0.01f);
    __syncthreads();

    auto force = [&](float Iv) -> float {
        float s = Iv;
        #pragma unroll
        for (int o = 16; o > 0; o >>= 1) s += __shfl_xor_sync(0xffffffffu, s, o);
        if (lane == 0) red[warp] = s;
        __syncthreads();
        float sumI = red[0]+red[1]+red[2]+red[3]+red[4]+red[5]+red[6]+red[7];
        float Ibar = sumI * (1.f/256.f);
        int qi = __float2int_rn((Iv - Ibar) * 127.f);
        qi = max(-127, min(127, qi));
        ((signed char*)Ipk)[t] = (signed char)qi;
        __syncthreads();
        int a0 = 0, a1 = 0, a2 = 0, a3 = 0;
        #pragma unroll
        for (int g = 0; g < 64; g += 4) {
            uint4 w = *(const uint4*)&Ipk[g];
            a0 = __dp4a((int)w.x, (int)qw[g+0], a0);
            a1 = __dp4a((int)w.y, (int)qw[g+1], a1);
            a2 = __dp4a((int)w.z, (int)qw[g+2], a2);
            a3 = __dp4a((int)w.w, (int)qw[g+3], a3);
        }
        float resid = (float)(a0 + a1 + a2 + a3) * fscale;
        return (sumI + Ibar * C + resid) * (1.f/256.f);
    };

    for (int w = 0; w < HOR; ++w) {
        for (int st = 0; st < 4; ++st) {
            float f1 = force(I);
            float ni = beta * S * f1;
            float dS1 = -ni, dE1 = ni - sg*E, dI1 = sg*E - gm*I;
            float S2 = S + 0.125f*dS1, E2 = E + 0.125f*dE1, I2 = I + 0.125f*dI1;
            float f2 = force(I2); ni = beta * S2 * f2;
            float dS2 = -ni, dE2 = ni - sg*E2, dI2 = sg*E2 - gm*I2;
            float S3 = S + 0.125f*dS2, E3 = E + 0.125f*dE2, I3 = I + 0.125f*dI2;
            float f3 = force(I3); ni = beta * S3 * f3;
            float dS3 = -ni, dE3 = ni - sg*E3, dI3 = sg*E3 - gm*I3;
            float S4 = S + 0.25f*dS3, E4 = E + 0.25f*dE3, I4 = I + 0.25f*dI3;
            float f4 = force(I4); ni = beta * S4 * f4;
            float dS4 = -ni, dE4 = ni - sg*E4, dI4 = sg*E4 - gm*I4;
            const float c = 0.25f / 6.f;
            S = fminf(fmaxf(S + c*(dS1 + 2.f*dS2 + 2.f*dS3 + dS4), 0.f), 1.f);
            E = fminf(fmaxf(E + c*(dE1 + 2.f*dE2 + 2.f*dE3 + dE4), 0.f), 1.f);
            I = fminf(fmaxf(I + c*(dI1 + 2.f*dI2 + 2.f*dI3 + dI4), 0.f), 1.f);
        }
        out[OUT_I + ((size_t)b*HOR + w)*256 + t] = I;
        out[OUT_E + ((size_t)b*HOR + w)*256 + t] = E;
    }
}

extern "C" void kernel_launch(void* const* d_in, const int* in_sizes, int n_in,
                              void* d_out, int out_size) {
    const float* x    = (const float*)d_in[0];
    const float* cnn  = (const float*)d_in[1];
    const float* W1   = (const float*)d_in[2];
    const float* b1   = (const float*)d_in[3];
    const float* W2   = (const float*)d_in[4];
    const float* b2   = (const float*)d_in[5];
    const float* M1   = (const float*)d_in[6];
    const float* mb1  = (const float*)d_in[7];
    const float* M2   = (const float*)d_in[8];
    const float* mb2  = (const float*)d_in[9];
    float* out = (float*)d_out;

    static cudaStream_t s2 = nullptr;
    static cudaEvent_t evA = nullptr, evB = nullptr, evD = nullptr;
    if (!s2) {
        cudaStreamCreateWithFlags(&s2, cudaStreamNonBlocking);
        cudaEventCreateWithFlags(&evA, cudaEventDisableTiming);
        cudaEventCreateWithFlags(&evB, cudaEventDisableTiming);
        cudaEventCreateWithFlags(&evD, cudaEventDisableTiming);
        cudaFuncSetAttribute(k4, cudaFuncAttributeMaxDynamicSharedMemorySize, K4_SMEM);
    }

    // main: zero, then fork
    k0_zero<<<(OUT_ZN + 255)/256, 256>>>(out);
    cudaEventRecord(evA, 0);
    cudaStreamWaitEvent(s2, evA, 0);

    // s2: M2 quantization (independent of everything else)
    k3c<<<256, 256, 0, s2>>>(M2);

    // main: mobility hidden + quantize (needed by k4)
    k3<<<dim3(2, 8), 256>>>(cnn, M1, mb1);
    k3b<<<64, 256>>>();
    cudaEventRecord(evB, 0);

    // s2: big softmax/D kernel
    cudaStreamWaitEvent(s2, evB, 0);
    k4<<<dim3(256, 8), 256, K4_SMEM, s2>>>(mb2, out);
    cudaEventRecord(evD, s2);

    // main: param branch
    k1<<<dim3(4, 64), 256>>>(x, W1);
    k1b<<<256, 256>>>(b1);
    k2<<<dim3(8, 8), 256>>>(W2, b2, out);

    // join, then sim
    cudaStreamWaitEvent(0, evD, 0);
    k5<<<512, 256>>>(x, out);
}

// round 7
// speedup vs baseline: 3.6591x; 1.0406x over previous
#include <cuda_runtime.h>
#include <cuda_fp16.h>
#include <math.h>

#define NB 512
#define HOR 12

// output layout (floats): I_sim, E_sim, beta.mean, sigma.mean, gamma.mean, Pi.mean
#define OUT_I  0
#define OUT_E  (NB*HOR*256)
#define OUT_BM (2*NB*HOR*256)
#define OUT_PI (OUT_BM + 768)
#define OUT_ZN (768 + 65536)

__device__ float g_hsum[NB*128];                 // param hidden (post-relu)
__device__ float g_hm[NB*128];                   // mobility hidden
__device__ float g_beta[NB*256];
__device__ float g_sigma[NB*256];
__device__ float g_gamma[NB*256];
__device__ float g_e0[NB*256];
__device__ __align__(16) __half g_D[(size_t)NB*256*256];   // D = 256*Pi - 1
__device__ float g_part[64*65536];               // k1 split-k partials (16 MB)
__device__ unsigned g_qh[NB*32];                 // int8-packed hm rows
__device__ float g_sh[NB];                       // hm row scales
__device__ __align__(16) unsigned g_qm[(size_t)256*8192];  // int8 M2, [icol][q][j]
__device__ float g_sm[65536];                    // M2 column scales

// ---------- K0: zero output means region ----------
__global__ void k0_zero(float* out) {
    int i = blockIdx.x * blockDim.x + threadIdx.x;
    if (i < OUT_ZN) out[OUT_BM + i] = 0.f;
}

// ---------- K1: partials[kz] = x @ W1 chunk (tile 128x128, acc 8x8) ----------
__global__ __launch_bounds__(256) void k1(const float* __restrict__ x,
                                          const float* __restrict__ W1) {
    __shared__ __align__(16) float sa[16*132];
    __shared__ __align__(16) float sw[16*128];
    int t = threadIdx.x, rg = t >> 4, cg = t & 15;
    int B0 = blockIdx.x * 128, kz = blockIdx.y;
    float acc[8][8] = {};
    for (int kt = 0; kt < 4; ++kt) {
        int k0 = kz*64 + kt*16;
        #pragma unroll
        for (int i = t; i < 512; i += 256) {
            int r = i >> 2, kq = i & 3;
            float4 v = *(const float4*)&x[(size_t)(B0 + r)*4096 + k0 + kq*4];
            sa[(kq*4+0)*132 + r] = v.x;
            sa[(kq*4+1)*132 + r] = v.y;
            sa[(kq*4+2)*132 + r] = v.z;
            sa[(kq*4+3)*132 + r] = v.w;
        }
        #pragma unroll
        for (int i = t; i < 512; i += 256) {
            int kk = i >> 5, c4 = i & 31;
            *(float4*)&sw[kk*128 + c4*4] =
                *(const float4*)&W1[(size_t)(k0 + kk)*128 + c4*4];
        }
        __syncthreads();
        #pragma unroll
        for (int kk = 0; kk < 16; ++kk) {
            float4 a0 = *(const float4*)&sa[kk*132 + rg*8];
            float4 a1 = *(const float4*)&sa[kk*132 + rg*8 + 4];
            float4 b0 = *(const float4*)&sw[kk*128 + cg*8];
            float4 b1 = *(const float4*)&sw[kk*128 + cg*8 + 4];
            float av[8] = {a0.x,a0.y,a0.z,a0.w,a1.x,a1.y,a1.z,a1.w};
            float bv[8] = {b0.x,b0.y,b0.z,b0.w,b1.x,b1.y,b1.z,b1.w};
            #pragma unroll
            for (int i = 0; i < 8; i++)
                #pragma unroll
                for (int q = 0; q < 8; q++)
                    acc[i][q] = fmaf(av[i], bv[q], acc[i][q]);
        }
        __syncthreads();
    }
    float* dst = g_part + (size_t)kz*65536;
    #pragma unroll
    for (int i = 0; i < 8; i++) {
        int r = B0 + rg*8 + i;
        *(float4*)&dst[r*128 + cg*8]     = make_float4(acc[i][0],acc[i][1],acc[i][2],acc[i][3]);
        *(float4*)&dst[r*128 + cg*8 + 4] = make_float4(acc[i][4],acc[i][5],acc[i][6],acc[i][7]);
    }
}

// ---------- K1b: h = relu(sum_k partials + b1) ----------
__global__ void k1b(const float* __restrict__ b1) {
    int i = blockIdx.x * blockDim.x + threadIdx.x;
    float s = 0.f;
    #pragma unroll
    for (int ks = 0; ks < 64; ++ks) s += g_part[(size_t)ks*65536 + i];
    g_hsum[i] = fmaxf(s + b1[i & 127], 0.f);
}

// ---------- K2: params = h @ W2 + b2 -> activations + means ----------
__global__ __launch_bounds__(256) void k2(const float* __restrict__ W2,
                                          const float* __restrict__ b2,
                                          float* out) {
    __shared__ __align__(16) float sa[16*68];
    __shared__ __align__(16) float sw[16*128];
    int t = threadIdx.x, rg = t >> 4, cg = t & 15;
    int C0 = blockIdx.x * 128, B0 = blockIdx.y * 64;
    float acc[4][8] = {};
    for (int kt = 0; kt < 8; ++kt) {
        int k0 = kt*16;
        {
            int i = t;
            int r = i >> 2, kq = i & 3;
            float4 v = *(const float4*)&g_hsum[(B0 + r)*128 + k0 + kq*4];
            sa[(kq*4+0)*68 + r] = v.x;
            sa[(kq*4+1)*68 + r] = v.y;
            sa[(kq*4+2)*68 + r] = v.z;
            sa[(kq*4+3)*68 + r] = v.w;
        }
        #pragma unroll
        for (int i = t; i < 512; i += 256) {
            int kk = i >> 5, c4 = i & 31;
            *(float4*)&sw[kk*128 + c4*4] =
                *(const float4*)&W2[(size_t)(k0 + kk)*1024 + C0 + c4*4];
        }
        __syncthreads();
        #pragma unroll
        for (int kk = 0; kk < 16; ++kk) {
            float4 a  = *(const float4*)&sa[kk*68 + rg*4];
            float4 b0 = *(const float4*)&sw[kk*128 + cg*8];
            float4 b1 = *(const float4*)&sw[kk*128 + cg*8 + 4];
            float av[4] = {a.x,a.y,a.z,a.w};
            float bv[8] = {b0.x,b0.y,b0.z,b0.w,b1.x,b1.y,b1.z,b1.w};
            #pragma unroll
            for (int i = 0; i < 4; i++)
                #pragma unroll
                for (int q = 0; q < 8; q++)
                    acc[i][q] = fmaf(av[i], bv[q], acc[i][q]);
        }
        __syncthreads();
    }
    int grp = C0 >> 8;
    float scl = (grp == 0) ? 3.f : (grp == 3) ? 5.f : 1.f;
    float* dst = (grp == 0) ? g_beta : (grp == 1) ? g_sigma : (grp == 2) ? g_gamma : g_e0;
    #pragma unroll
    for (int i = 0; i < 4; i++) {
        int rb = B0 + rg*4 + i;
        #pragma unroll
        for (int q = 0; q < 8; q++) {
            int cgg = C0 + cg*8 + q;
            float s = scl / (1.f + __expf(-(acc[i][q] + b2[cgg])));
            int col = cgg & 255;
            dst[rb*256 + col] = s;
            if (grp < 3) atomicAdd(&out[OUT_BM + grp*256 + col], s * (1.f/512.f));
        }
    }
}

// ---------- K3: hm = relu(cnn @ M1 + mb1) ----------
__global__ __launch_bounds__(256) void k3(const float* __restrict__ cnn,
                                          const float* __restrict__ M1,
                                          const float* __restrict__ mb1) {
    __shared__ __align__(16) float sa[16*68], sw[16*64];
    int t = threadIdx.x, rg = t >> 4, cg = t & 15;
    int B0 = blockIdx.y*64, C0 = blockIdx.x*64;
    float acc[4][4] = {};
    for (int kt = 0; kt < 64; kt += 16) {
        #pragma unroll
        for (int i = t; i < 64*16; i += 256) {
            int r = i >> 4, kk = i & 15;
            sa[kk*68 + r] = cnn[(size_t)(B0 + r)*64 + kt + kk];
        }
        #pragma unroll
        for (int i = t; i < 16*64; i += 256) {
            int kk = i >> 6, c = i & 63;
            sw[kk*64 + c] = M1[(size_t)(kt + kk)*128 + C0 + c];
        }
        __syncthreads();
        #pragma unroll
        for (int kk = 0; kk < 16; ++kk) {
            float4 a = *(const float4*)&sa[kk*68 + rg*4];
            float4 w = *(const float4*)&sw[kk*64 + cg*4];
            float av[4] = {a.x,a.y,a.z,a.w}, wv[4] = {w.x,w.y,w.z,w.w};
            #pragma unroll
            for (int i = 0; i < 4; i++)
                #pragma unroll
                for (int q = 0; q < 4; q++)
                    acc[i][q] = fmaf(av[i], wv[q], acc[i][q]);
        }
        __syncthreads();
    }
    #pragma unroll
    for (int i = 0; i < 4; i++)
        #pragma unroll
        for (int q = 0; q < 4; q++) {
            int c = C0 + cg*4 + q;
            g_hm[(B0 + rg*4 + i)*128 + c] = fmaxf(acc[i][q] + mb1[c], 0.f);
        }
}

// ---------- K3b: quantize hm rows to int8 (warp = one row) ----------
__global__ void k3b() {
    int lane = threadIdx.x & 31, warp = threadIdx.x >> 5;
    int row = blockIdx.x*8 + warp;
    float4 v = *(const float4*)&g_hm[row*128 + lane*4];
    float mx = fmaxf(fmaxf(v.x, v.y), fmaxf(v.z, v.w));
    #pragma unroll
    for (int o = 16; o > 0; o >>= 1) mx = fmaxf(mx, __shfl_xor_sync(0xffffffffu, mx, o));
    float inv = mx > 0.f ? 127.f/mx : 0.f;
    int q0 = __float2int_rn(v.x*inv), q1 = __float2int_rn(v.y*inv);
    int q2 = __float2int_rn(v.z*inv), q3 = __float2int_rn(v.w*inv);
    unsigned w = (unsigned)(q0 & 255) | ((unsigned)(q1 & 255) << 8) |
                 ((unsigned)(q2 & 255) << 16) | ((unsigned)(q3 & 255) << 24);
    g_qh[row*32 + lane] = w;
    if (lane == 0) g_sh[row] = mx * (1.f/127.f);
}

// ---------- K3c: quantize M2 per output column -> g_qm[icol][q][j] ----------
__global__ __launch_bounds__(256) void k3c(const float* __restrict__ M2) {
    int j = threadIdx.x, icol = blockIdx.x;
    const float* base = M2 + (size_t)icol*256 + j;
    float mx = 0.f;
    #pragma unroll 8
    for (int k = 0; k < 128; ++k) mx = fmaxf(mx, fabsf(base[(size_t)k*65536]));
    float inv = mx > 0.f ? 127.f/mx : 0.f;
    g_sm[icol*256 + j] = mx * (1.f/127.f);
    for (int q = 0; q < 32; ++q) {
        unsigned w = 0;
        #pragma unroll
        for (int e = 0; e < 4; ++e) {
            float v = base[(size_t)(4*q + e)*65536];
            int qi = __float2int_rn(v*inv);
            qi = max(-127, min(127, qi));
            w |= ((unsigned)(qi & 255)) << (8*e);
        }
        g_qm[(size_t)icol*8192 + q*256 + j] = w;
    }
}

// ---------- K4: int8 IMMA (mma.sync m16n8k32) logits + softmax + D + Pi.mean ----------
// CTA = (icol, 64 b-rows). 8 warps: mw = w&3 -> 16-row block, nh = w>>2 -> 128-col half.
// smem u32 offsets:
//   qhS 0..2112, qmS 2112..10432, smjS 10432, mbjS 10688, shS 10944,
//   rs 11008 (2*64), psum 11136 (8*256) -> total 13184 u32 = 52736 B
#define K4_SMEM (13184 * 4)
__global__ __launch_bounds__(256, 2) void k4(const float* __restrict__ mb2,
                                             float* out) {
    extern __shared__ __align__(16) unsigned smu[];
    unsigned* qhS = smu;                 // [64][33]
    unsigned* qmS = smu + 2112;          // [32][260]
    float* smjS = (float*)(smu + 10432); // [256]
    float* mbjS = (float*)(smu + 10688); // [256]
    float* shS  = (float*)(smu + 10944); // [64]
    float* rs   = (float*)(smu + 11008); // [2][64]
    float* psum = (float*)(smu + 11136); // [8][256]
    int t = threadIdx.x;
    int icol = blockIdx.x, B0 = blockIdx.y * 64;
    int w = t >> 5, lane = t & 31;
    int mw = w & 3, nh = w >> 2;
    int r = lane >> 2, c = lane & 3;
    int m0 = mw * 16;

    #pragma unroll
    for (int i = t; i < 2048; i += 256) {
        int b = i >> 5, q = i & 31;
        qhS[b*33 + q] = g_qh[(B0 + b)*32 + q];
    }
    {
        const uint4* src = (const uint4*)(g_qm + (size_t)icol*8192);
        #pragma unroll
        for (int i = t; i < 2048; i += 256) {
            int q = i >> 6, j4 = i & 63;
            *(uint4*)&qmS[q*260 + j4*4] = src[i];
        }
    }
    smjS[t] = g_sm[icol*256 + t];
    mbjS[t] = mb2[(size_t)icol*256 + t];
    if (t < 64) shS[t] = g_sh[B0 + t];
    #pragma unroll
    for (int i = t; i < 2048; i += 256) psum[i] = 0.f;
    __syncthreads();

    int acc[16][4] = {};
    #pragma unroll
    for (int kt = 0; kt < 4; ++kt) {
        int a0 = (int)qhS[(m0 + r)*33     + kt*8 + c];
        int a1 = (int)qhS[(m0 + r + 8)*33 + kt*8 + c];
        int a2 = (int)qhS[(m0 + r)*33     + kt*8 + 4 + c];
        int a3 = (int)qhS[(m0 + r + 8)*33 + kt*8 + 4 + c];
        #pragma unroll
        for (int nt = 0; nt < 16; ++nt) {
            int ncol = nh*128 + nt*8 + r;
            int b0 = (int)qmS[(kt*8 + c)*260 + ncol];
            int b1 = (int)qmS[(kt*8 + 4 + c)*260 + ncol];
            asm volatile(
                "mma.sync.aligned.m16n8k32.row.col.s32.s8.s8.s32 "
                "{%0,%1,%2,%3}, {%4,%5,%6,%7}, {%8,%9}, {%0,%1,%2,%3};"
                : "+r"(acc[nt][0]), "+r"(acc[nt][1]), "+r"(acc[nt][2]), "+r"(acc[nt][3])
                : "r"(a0), "r"(a1), "r"(a2), "r"(a3), "r"(b0), "r"(b1));
        }
    }

    // epilogue: exp + row sums (rows m0+r and m0+r+8)
    float shA = shS[m0 + r], shB = shS[m0 + r + 8];
    float sA = 0.f, sB = 0.f;
    #pragma unroll
    for (int nt = 0; nt < 16; ++nt) {
        int j0 = nh*128 + nt*8 + 2*c;
        float sj0 = smjS[j0], sj1 = smjS[j0 + 1];
        float m0b = mbjS[j0], m1b = mbjS[j0 + 1];
        float e00 = __expf((float)acc[nt][0] * (shA*sj0) + m0b);
        float e01 = __expf((float)acc[nt][1] * (shA*sj1) + m1b);
        float e10 = __expf((float)acc[nt][2] * (shB*sj0) + m0b);
        float e11 = __expf((float)acc[nt][3] * (shB*sj1) + m1b);
        sA += e00 + e01;  sB += e10 + e11;
        acc[nt][0] = __float_as_int(e00);
        acc[nt][1] = __float_as_int(e01);
        acc[nt][2] = __float_as_int(e10);
        acc[nt][3] = __float_as_int(e11);
    }
    sA += __shfl_xor_sync(0xffffffffu, sA, 1);
    sA += __shfl_xor_sync(0xffffffffu, sA, 2);
    sB += __shfl_xor_sync(0xffffffffu, sB, 1);
    sB += __shfl_xor_sync(0xffffffffu, sB, 2);
    if (c == 0) {
        rs[nh*64 + m0 + r] = sA;
        rs[nh*64 + m0 + r + 8] = sB;
    }
    __syncthreads();
    float invA = 1.f / (rs[m0 + r] + rs[64 + m0 + r]);
    float invB = 1.f / (rs[m0 + r + 8] + rs[64 + m0 + r + 8]);

    __half* dpA = g_D + ((size_t)(B0 + m0 + r)*256 + icol)*256;
    __half* dpB = g_D + ((size_t)(B0 + m0 + r + 8)*256 + icol)*256;
    #pragma unroll
    for (int nt = 0; nt < 16; ++nt) {
        int j0 = nh*128 + nt*8 + 2*c;
        float pA0 = __int_as_float(acc[nt][0]) * invA;
        float pA1 = __int_as_float(acc[nt][1]) * invA;
        float pB0 = __int_as_float(acc[nt][2]) * invB;
        float pB1 = __int_as_float(acc[nt][3]) * invB;
        *(__half2*)(dpA + j0) = __floats2half2_rn(fmaf(pA0, 256.f, -1.f), fmaf(pA1, 256.f, -1.f));
        *(__half2*)(dpB + j0) = __floats2half2_rn(fmaf(pB0, 256.f, -1.f), fmaf(pB1, 256.f, -1.f));
        float pm0 = pA0 + pB0, pm1 = pA1 + pB1;
        pm0 += __shfl_xor_sync(0xffffffffu, pm0, 4);
        pm0 += __shfl_xor_sync(0xffffffffu, pm0, 8);
        pm0 += __shfl_xor_sync(0xffffffffu, pm0, 16);
        pm1 += __shfl_xor_sync(0xffffffffu, pm1, 4);
        pm1 += __shfl_xor_sync(0xffffffffu, pm1, 8);
        pm1 += __shfl_xor_sync(0xffffffffu, pm1, 16);
        if (r == 0) {
            psum[w*256 + j0] = pm0;
            psum[w*256 + j0 + 1] = pm1;
        }
    }
    __syncthreads();
    float s2 = 0.f;
    #pragma unroll
    for (int g = 0; g < 8; g++) s2 += psum[g*256 + t];
    atomicAdd(&out[OUT_PI + icol*256 + t], s2 * (1.f/512.f));
}

// ---------- K5: RK4 SEIR sim, register-resident int8 D + DP4A, 1 bar/eval ----------
__global__ __launch_bounds__(256, 2) void k5(const float* __restrict__ x,
                                             float* __restrict__ out) {
    __shared__ float red[2][8];
    __shared__ float rmax[8];
    __shared__ __align__(16) unsigned Ipk[2][64];
    int t = threadIdx.x, b = blockIdx.x;
    int lane = t & 31, warp = t >> 5;

    const __half* Dg = g_D + (size_t)b * 65536 + t;

    float C = 0.f, mx = 0.f;
    #pragma unroll 8
    for (int n = 0; n < 256; ++n) {
        float v = __half2float(__ldg(Dg + (size_t)n * 256));
        C += v; mx = fmaxf(mx, fabsf(v));
    }
    #pragma unroll
    for (int o = 16; o > 0; o >>= 1) mx = fmaxf(mx, __shfl_xor_sync(0xffffffffu, mx, o));
    if (lane == 0) rmax[warp] = mx;
    __syncthreads();
    float m8 = rmax[0];
    #pragma unroll
    for (int w = 1; w < 8; ++w) m8 = fmaxf(m8, rmax[w]);
    float sD = fmaxf(m8, 1e-8f) * (1.f/127.f);
    float invsD = 1.f / sD;
    const float fscale = sD * (1.f/127.f);

    unsigned qw[64];
    #pragma unroll
    for (int g = 0; g < 64; ++g) {
        unsigned w = 0;
        #pragma unroll
        for (int kk = 0; kk < 4; ++kk) {
            float v = __half2float(__ldg(Dg + (size_t)(g*4 + kk) * 256));
            int q = __float2int_rn(v * invsD);
            q = max(-127, min(127, q));
            w |= ((unsigned)(q & 255)) << (8*kk);
        }
        qw[g] = w;
    }

    float beta = g_beta[b*256 + t], sg = g_sigma[b*256 + t];
    float gm   = g_gamma[b*256 + t], e0r = g_e0[b*256 + t];
    float I = fmaxf(x[(size_t)b*4096 + 15*256 + t], 1e-6f);
    float E = I * e0r;
    float S = fmaxf(1.f - E - I, 0.01f);
    __syncthreads();

    int ec = 0;
    auto force = [&](float Iv) -> float {
        int buf = ec & 1;  ec ^= 1;
        // quantize (Iv - 0.5), always in [-0.5, 0.5]
        int qi = __float2int_rn((Iv - 0.5f) * 127.f);
        ((signed char*)Ipk[buf])[t] = (signed char)qi;
        float s = Iv;
        #pragma unroll
        for (int o = 16; o > 0; o >>= 1) s += __shfl_xor_sync(0xffffffffu, s, o);
        if (lane == 0) red[buf][warp] = s;
        __syncthreads();
        float sumI = red[buf][0]+red[buf][1]+red[buf][2]+red[buf][3]
                   + red[buf][4]+red[buf][5]+red[buf][6]+red[buf][7];
        int a0 = 0, a1 = 0, a2 = 0, a3 = 0;
        const unsigned* ip = Ipk[buf];
        #pragma unroll
        for (int g = 0; g < 64; g += 4) {
            uint4 wv = *(const uint4*)&ip[g];
            a0 = __dp4a((int)wv.x, (int)qw[g+0], a0);
            a1 = __dp4a((int)wv.y, (int)qw[g+1], a1);
            a2 = __dp4a((int)wv.z, (int)qw[g+2], a2);
            a3 = __dp4a((int)wv.w, (int)qw[g+3], a3);
        }
        float resid = (float)(a0 + a1 + a2 + a3) * fscale;
        return (sumI + 0.5f * C + resid) * (1.f/256.f);
    };

    for (int w = 0; w < HOR; ++w) {
        for (int st = 0; st < 4; ++st) {
            float f1 = force(I);
            float ni = beta * S * f1;
            float dS1 = -ni, dE1 = ni - sg*E, dI1 = sg*E - gm*I;
            float S2 = S + 0.125f*dS1, E2 = E + 0.125f*dE1, I2 = I + 0.125f*dI1;
            float f2 = force(I2); ni = beta * S2 * f2;
            float dS2 = -ni, dE2 = ni - sg*E2, dI2 = sg*E2 - gm*I2;
            float S3 = S + 0.125f*dS2, E3 = E + 0.125f*dE2, I3 = I + 0.125f*dI2;
            float f3 = force(I3); ni = beta * S3 * f3;
            float dS3 = -ni, dE3 = ni - sg*E3, dI3 = sg*E3 - gm*I3;
            float S4 = S + 0.25f*dS3, E4 = E + 0.25f*dE3, I4 = I + 0.25f*dI3;
            float f4 = force(I4); ni = beta * S4 * f4;
            float dS4 = -ni, dE4 = ni - sg*E4, dI4 = sg*E4 - gm*I4;
            const float c = 0.25f / 6.f;
            S = fminf(fmaxf(S + c*(dS1 + 2.f*dS2 + 2.f*dS3 + dS4), 0.f), 1.f);
            E = fminf(fmaxf(E + c*(dE1 + 2.f*dE2 + 2.f*dE3 + dE4), 0.f), 1.f);
            I = fminf(fmaxf(I + c*(dI1 + 2.f*dI2 + 2.f*dI3 + dI4), 0.f), 1.f);
        }
        out[OUT_I + ((size_t)b*HOR + w)*256 + t] = I;
        out[OUT_E + ((size_t)b*HOR + w)*256 + t] = E;
    }
}

extern "C" void kernel_launch(void* const* d_in, const int* in_sizes, int n_in,
                              void* d_out, int out_size) {
    const float* x    = (const float*)d_in[0];
    const float* cnn  = (const float*)d_in[1];
    const float* W1   = (const float*)d_in[2];
    const float* b1   = (const float*)d_in[3];
    const float* W2   = (const float*)d_in[4];
    const float* b2   = (const float*)d_in[5];
    const float* M1   = (const float*)d_in[6];
    const float* mb1  = (const float*)d_in[7];
    const float* M2   = (const float*)d_in[8];
    const float* mb2  = (const float*)d_in[9];
    float* out = (float*)d_out;

    static cudaStream_t s2 = nullptr;
    static cudaEvent_t evA = nullptr, evB = nullptr, evD = nullptr;
    if (!s2) {
        cudaStreamCreateWithFlags(&s2, cudaStreamNonBlocking);
        cudaEventCreateWithFlags(&evA, cudaEventDisableTiming);
        cudaEventCreateWithFlags(&evB, cudaEventDisableTiming);
        cudaEventCreateWithFlags(&evD, cudaEventDisableTiming);
        cudaFuncSetAttribute(k4, cudaFuncAttributeMaxDynamicSharedMemorySize, K4_SMEM);
    }

    // s2 kicks off M2 quantization immediately (longest pre-k4 dependency)
    cudaEventRecord(evA, 0);
    cudaStreamWaitEvent(s2, evA, 0);
    k3c<<<256, 256, 0, s2>>>(M2);

    // main: zero + mobility hidden + hm quantize
    k0_zero<<<(OUT_ZN + 255)/256, 256>>>(out);
    k3<<<dim3(2, 8), 256>>>(cnn, M1, mb1);
    k3b<<<64, 256>>>();
    cudaEventRecord(evB, 0);

    // s2: IMMA softmax/D kernel
    cudaStreamWaitEvent(s2, evB, 0);
    k4<<<dim3(256, 8), 256, K4_SMEM, s2>>>(mb2, out);
    cudaEventRecord(evD, s2);

    // main: param branch (concurrent with k4)
    k1<<<dim3(4, 64), 256>>>(x, W1);
    k1b<<<256, 256>>>(b1);
    k2<<<dim3(8, 8), 256>>>(W2, b2, out);

    // join, then sim
    cudaStreamWaitEvent(0, evD, 0);
    k5<<<512, 256>>>(x, out);
}